// round 7
// baseline (speedup 1.0000x reference)
#include <cuda_runtime.h>
#include <cuda_bf16.h>
#include <cstdint>

#define NN    8192
#define DIN   512
#define DOUT  512

// ---------------- helpers ----------------
__device__ __forceinline__ uint32_t smem_to_u32(const void* p) {
    uint32_t a;
    asm("{ .reg .u64 t; cvta.to.shared.u64 t, %1; cvt.u32.u64 %0, t; }" : "=r"(a) : "l"(p));
    return a;
}

#define CP_ASYNC16(dst, src) \
    asm volatile("cp.async.cg.shared.global [%0], [%1], 16;" :: "r"(dst), "l"(src) : "memory")
#define CP_COMMIT() asm volatile("cp.async.commit_group;" ::: "memory")
#define CP_WAIT0()  asm volatile("cp.async.wait_group 0;" ::: "memory")
#define CP_WAIT1()  asm volatile("cp.async.wait_group 1;" ::: "memory")

#define LDS32(v, addr) \
    asm volatile("ld.shared.b32 %0, [%1];" : "=r"(v) : "r"(addr))

__device__ __forceinline__ void mma16816(float* c, const uint32_t* a, uint32_t b0, uint32_t b1) {
    asm volatile(
        "mma.sync.aligned.m16n8k16.row.col.f32.bf16.bf16.f32 "
        "{%0,%1,%2,%3}, {%4,%5,%6,%7}, {%8,%9}, {%0,%1,%2,%3};"
        : "+f"(c[0]), "+f"(c[1]), "+f"(c[2]), "+f"(c[3])
        : "r"(a[0]), "r"(a[1]), "r"(a[2]), "r"(a[3]), "r"(b0), "r"(b1));
}

// ---------------- device-global scratch ----------------
__device__ __align__(256) __nv_bfloat16 g_xTh[(size_t)DIN * NN];   // x^T hi  [512,8192]
__device__ __align__(256) __nv_bfloat16 g_xTl[(size_t)DIN * NN];   // x^T lo
__device__ __align__(256) __nv_bfloat16 g_A2[(size_t)NN * 1536];   // [x_hi | x_lo | x_hi]
__device__ __align__(256) __nv_bfloat16 g_A3[(size_t)NN * 1536];   // [agg_hi | agg_lo | agg_hi]
__device__ __align__(256) __nv_bfloat16 g_A4[(size_t)NN * 3072];   // [c_hi | c_lo | c_hi]
__device__ __align__(256) __nv_bfloat16 g_Bt2[(size_t)DOUT * 1536];
__device__ __align__(256) __nv_bfloat16 g_Bt3[(size_t)DOUT * 1536];
__device__ __align__(256) __nv_bfloat16 g_Bt4[(size_t)DOUT * 3072];
__device__ __align__(256) float g_S1[(size_t)NN * DOUT];
__device__ __align__(256) float g_deg[NN];

__device__ __forceinline__ void split_hl(float v, __nv_bfloat16& h, __nv_bfloat16& l) {
    h = __float2bfloat16(v);
    l = __float2bfloat16(v - __bfloat162float(h));
}

// ---------------- prep: x -> A2 cat + transposed hi/lo ----------------
__global__ void prep_x_kernel(const float* __restrict__ x) {
    __shared__ __nv_bfloat16 sh[32][33], sl[32][33];
    int tx = threadIdx.x, ty = threadIdx.y;
    int d0 = blockIdx.x * 32, m0 = blockIdx.y * 32;
#pragma unroll
    for (int r = 0; r < 4; r++) {
        int mm = ty + r * 8, m = m0 + mm;
        float v = x[(size_t)m * DIN + d0 + tx];
        __nv_bfloat16 h, l; split_hl(v, h, l);
        size_t rb = (size_t)m * 1536 + d0 + tx;
        g_A2[rb] = h; g_A2[rb + 512] = l; g_A2[rb + 1024] = h;
        sh[mm][tx] = h; sl[mm][tx] = l;
    }
    __syncthreads();
#pragma unroll
    for (int r = 0; r < 4; r++) {
        int dd = ty + r * 8, d = d0 + dd, m = m0 + tx;
        g_xTh[(size_t)d * NN + m] = sh[tx][dd];
        g_xTl[(size_t)d * NN + m] = sl[tx][dd];
    }
}

// ---------------- prep: weights -> transposed hi/lo K-concats ----------------
__global__ void prep_w_kernel(const float* __restrict__ Ws, const float* __restrict__ Wn,
                              const float* __restrict__ Wc) {
    int t = blockIdx.x * blockDim.x + threadIdx.x;  // 512*1024 threads
    int n = t & 511, k = t >> 9;
    __nv_bfloat16 h, l;
    if (k < 512) {
        size_t rb = (size_t)n * 1536 + k;
        split_hl(Ws[(size_t)k * DOUT + n], h, l);
        g_Bt2[rb] = h; g_Bt2[rb + 512] = h; g_Bt2[rb + 1024] = l;
        split_hl(Wn[(size_t)k * DOUT + n], h, l);
        g_Bt3[rb] = h; g_Bt3[rb + 512] = h; g_Bt3[rb + 1024] = l;
    }
    {
        size_t rb = (size_t)n * 3072 + k;
        split_hl(Wc[(size_t)k * DOUT + n], h, l);
        g_Bt4[rb] = h; g_Bt4[rb + 1024] = h; g_Bt4[rb + 2048] = l;
    }
}

// ---------------- agg = S1/max(deg,1) -> A3 cat ----------------
__global__ void agg_split_kernel() {
    int t = blockIdx.x * 256 + threadIdx.x;  // NN*128 threads
    int m = t >> 7, d4 = (t & 127) * 4;
    float inv = 1.0f / fmaxf(g_deg[m], 1.0f);
    float4 s = *reinterpret_cast<const float4*>(g_S1 + (size_t)m * DOUT + d4);
    __nv_bfloat16 h0, l0, h1, l1, h2, l2, h3, l3;
    split_hl(s.x * inv, h0, l0); split_hl(s.y * inv, h1, l1);
    split_hl(s.z * inv, h2, l2); split_hl(s.w * inv, h3, l3);
    size_t rb = (size_t)m * 1536 + d4;
    __nv_bfloat162* p;
    p = reinterpret_cast<__nv_bfloat162*>(g_A3 + rb);
    p[0] = __nv_bfloat162(h0, h1); p[1] = __nv_bfloat162(h2, h3);
    p = reinterpret_cast<__nv_bfloat162*>(g_A3 + rb + 512);
    p[0] = __nv_bfloat162(l0, l1); p[1] = __nv_bfloat162(l2, l3);
    p = reinterpret_cast<__nv_bfloat162*>(g_A3 + rb + 1024);
    p[0] = __nv_bfloat162(h0, h1); p[1] = __nv_bfloat162(h2, h3);
}

// ============================================================================
// Padded-linear smem layout: row stride 144 B (64 bf16 data + 16 B pad).
// Fragment regs loaded with plain LDS32 per the PTX m16n8k16 layouts:
//   a0=(m, k2), a1=(m+8, k2), a2=(m, k2+8), a3=(m+8, k2+8)  [k2 = s4*16 + 2*(lane%4)]
//   b0=(k2, n), b1=(k2+8, n)  with Bt[n][k] n-major/k-contiguous
// ============================================================================
static constexpr int RSTR = 144;
static constexpr int G1_AT = 128 * RSTR;            // 18432
static constexpr int G1_BT = 256 * RSTR;            // 36864
static constexpr int G1_STAGE = G1_AT + 2 * G1_BT;  // 92160
static constexpr int G1_SMEM  = 1024 + 2 * G1_STAGE;  // 185344

__global__ void __launch_bounds__(256, 1)
gemm1_kernel(const int* __restrict__ adj) {
    extern __shared__ char smem[];
    uint32_t sb = smem_to_u32(smem);
    int tid = threadIdx.x, wid = tid >> 5, lane = tid & 31;
    int m0 = blockIdx.y * 128, n0 = blockIdx.x * 256;
    bool dodeg = (blockIdx.x == 0);
    int* degsm = reinterpret_cast<int*>(smem);
    if (tid < 128) degsm[tid] = 0;

    const int wm = (wid & 3) * 32;     // warp m-offset
    const int wn = (wid >> 2) * 128;   // warp n-offset

    float c[2][16][4];
#pragma unroll
    for (int i = 0; i < 2; i++)
#pragma unroll
        for (int j = 0; j < 16; j++)
#pragma unroll
            for (int q = 0; q < 4; q++) c[i][j][q] = 0.0f;

    int4 av[4][2];
    int dacc[4] = {0, 0, 0, 0};

    auto ldA = [&](int k0) {
#pragma unroll
        for (int i = 0; i < 4; i++) {
            int idx = i * 256 + tid;
            int r = idx >> 3, cc = idx & 7;
            const int4* p = reinterpret_cast<const int4*>(
                adj + (size_t)(m0 + r) * NN + k0 + cc * 8);
            av[i][0] = p[0]; av[i][1] = p[1];
        }
    };
    auto stA = [&](uint32_t abase) {
#pragma unroll
        for (int i = 0; i < 4; i++) {
            int idx = i * 256 + tid;
            int r = idx >> 3, cc = idx & 7;
            uint32_t p0 = ((av[i][0].x > 0) ? 0x3F80u : 0u) | ((av[i][0].y > 0) ? 0x3F800000u : 0u);
            uint32_t p1 = ((av[i][0].z > 0) ? 0x3F80u : 0u) | ((av[i][0].w > 0) ? 0x3F800000u : 0u);
            uint32_t p2 = ((av[i][1].x > 0) ? 0x3F80u : 0u) | ((av[i][1].y > 0) ? 0x3F800000u : 0u);
            uint32_t p3 = ((av[i][1].z > 0) ? 0x3F80u : 0u) | ((av[i][1].w > 0) ? 0x3F800000u : 0u);
            if (dodeg)
                dacc[i] += (av[i][0].x > 0) + (av[i][0].y > 0) + (av[i][0].z > 0) + (av[i][0].w > 0)
                         + (av[i][1].x > 0) + (av[i][1].y > 0) + (av[i][1].z > 0) + (av[i][1].w > 0);
            asm volatile("st.shared.v4.b32 [%0], {%1,%2,%3,%4};"
                         :: "r"(abase + (uint32_t)(r * RSTR + cc * 16)),
                            "r"(p0), "r"(p1), "r"(p2), "r"(p3) : "memory");
        }
    };
    auto ldB = [&](uint32_t bbase, const __nv_bfloat16* __restrict__ src, int k0) {
#pragma unroll
        for (int i = 0; i < 8; i++) {
            int idx = i * 256 + tid;
            int r = idx >> 3, cc = idx & 7;
            CP_ASYNC16(bbase + (uint32_t)(r * RSTR + cc * 16),
                       reinterpret_cast<const char*>(src) + ((size_t)(n0 + r) * NN + k0 + cc * 8) * 2);
        }
    };
    auto compute = [&](uint32_t base) {
        uint32_t aBh = base + G1_AT, aBl = base + G1_AT + G1_BT;
        int tq = lane >> 2;          // 0..7
        int tr4 = (lane & 3) * 4;    // byte offset of k pair
#pragma unroll
        for (int s4 = 0; s4 < 4; s4++) {
            uint32_t a[2][4];
#pragma unroll
            for (int ms = 0; ms < 2; ms++) {
                uint32_t ad = base + (uint32_t)((wm + ms * 16 + tq) * RSTR + s4 * 32 + tr4);
                LDS32(a[ms][0], ad);
                LDS32(a[ms][1], ad + 8 * RSTR);
                LDS32(a[ms][2], ad + 16);
                LDS32(a[ms][3], ad + 8 * RSTR + 16);
            }
#pragma unroll
            for (int p = 0; p < 16; p++) {
                uint32_t bd = (uint32_t)((wn + p * 8 + tq) * RSTR + s4 * 32 + tr4);
                uint32_t b0, b1;
                LDS32(b0, aBh + bd); LDS32(b1, aBh + bd + 16);
                mma16816(c[0][p], a[0], b0, b1);
                mma16816(c[1][p], a[1], b0, b1);
                LDS32(b0, aBl + bd); LDS32(b1, aBl + bd + 16);
                mma16816(c[0][p], a[0], b0, b1);
                mma16816(c[1][p], a[1], b0, b1);
            }
        }
    };

    // prologue
    uint32_t st0 = sb + 1024;
    ldA(0);
    ldB(st0 + G1_AT, g_xTh, 0);
    ldB(st0 + G1_AT + G1_BT, g_xTl, 0);
    CP_COMMIT();
    stA(st0);

    const int NIT = NN / 64;  // 128
    for (int it = 0; it < NIT; it++) {
        int s = it & 1;
        uint32_t cur = sb + 1024 + s * G1_STAGE;
        uint32_t nxt = sb + 1024 + (1 - s) * G1_STAGE;
        bool more = (it + 1 < NIT);
        if (more) {
            int k0 = (it + 1) * 64;
            ldA(k0);
            ldB(nxt + G1_AT, g_xTh, k0);
            ldB(nxt + G1_AT + G1_BT, g_xTl, k0);
            CP_COMMIT();
            CP_WAIT1();
        } else {
            CP_WAIT0();
        }
        __syncthreads();
        compute(cur);
        if (more) stA(nxt);
        __syncthreads();
    }

    // epilogue: raw sums to g_S1
#pragma unroll
    for (int ms = 0; ms < 2; ms++) {
        int row = m0 + wm + ms * 16 + (lane >> 2);
#pragma unroll
        for (int ns = 0; ns < 16; ns++) {
            int col = n0 + wn + ns * 8 + 2 * (lane & 3);
            *reinterpret_cast<float2*>(g_S1 + (size_t)row * DOUT + col) =
                make_float2(c[ms][ns][0], c[ms][ns][1]);
            *reinterpret_cast<float2*>(g_S1 + (size_t)(row + 8) * DOUT + col) =
                make_float2(c[ms][ns][2], c[ms][ns][3]);
        }
    }
    if (dodeg) {
#pragma unroll
        for (int i = 0; i < 4; i++) atomicAdd(&degsm[(i * 256 + tid) >> 3], dacc[i]);
        __syncthreads();
        if (tid < 128) g_deg[m0 + tid] = (float)degsm[tid];
    }
}

// ============================================================================
// Small GEMMs: C[8192,512] = A[8192,Kcat] @ Bt[512,Kcat]^T + epilogue
// which: 0 self_f -> g_A4 cols [0,512); 1 nb_f -> g_A4 cols [512,1024);
//        2 final  -> bias+relu -> out
// ============================================================================
static constexpr int GS_STAGE = G1_AT + G1_BT;      // 55296
static constexpr int GS_SMEM  = 2 * GS_STAGE;       // 110592

__global__ void __launch_bounds__(256, 1)
gemm_small_kernel(int which, const float* __restrict__ bias, float* __restrict__ outf) {
    extern __shared__ char smem[];
    uint32_t sb = smem_to_u32(smem);
    int tid = threadIdx.x, wid = tid >> 5, lane = tid & 31;
    int m0 = blockIdx.y * 128, n0 = blockIdx.x * 256;

    const __nv_bfloat16 *A, *B;
    int Kcat;
    if (which == 0)      { A = g_A2; B = g_Bt2; Kcat = 1536; }
    else if (which == 1) { A = g_A3; B = g_Bt3; Kcat = 1536; }
    else                 { A = g_A4; B = g_Bt4; Kcat = 3072; }

    const int wm = (wid & 3) * 32, wn = (wid >> 2) * 128;

    float c[2][16][4];
#pragma unroll
    for (int i = 0; i < 2; i++)
#pragma unroll
        for (int j = 0; j < 16; j++)
#pragma unroll
            for (int q = 0; q < 4; q++) c[i][j][q] = 0.0f;

    auto ldA = [&](uint32_t abase, int k0) {
#pragma unroll
        for (int i = 0; i < 4; i++) {
            int idx = i * 256 + tid;
            int r = idx >> 3, cc = idx & 7;
            CP_ASYNC16(abase + (uint32_t)(r * RSTR + cc * 16),
                       reinterpret_cast<const char*>(A) + ((size_t)(m0 + r) * Kcat + k0 + cc * 8) * 2);
        }
    };
    auto ldB = [&](uint32_t bbase, int k0) {
#pragma unroll
        for (int i = 0; i < 8; i++) {
            int idx = i * 256 + tid;
            int r = idx >> 3, cc = idx & 7;
            CP_ASYNC16(bbase + (uint32_t)(r * RSTR + cc * 16),
                       reinterpret_cast<const char*>(B) + ((size_t)(n0 + r) * Kcat + k0 + cc * 8) * 2);
        }
    };
    auto compute = [&](uint32_t base) {
        uint32_t aB = base + G1_AT;
        int tq = lane >> 2;
        int tr4 = (lane & 3) * 4;
#pragma unroll
        for (int s4 = 0; s4 < 4; s4++) {
            uint32_t a[2][4];
#pragma unroll
            for (int ms = 0; ms < 2; ms++) {
                uint32_t ad = base + (uint32_t)((wm + ms * 16 + tq) * RSTR + s4 * 32 + tr4);
                LDS32(a[ms][0], ad);
                LDS32(a[ms][1], ad + 8 * RSTR);
                LDS32(a[ms][2], ad + 16);
                LDS32(a[ms][3], ad + 8 * RSTR + 16);
            }
#pragma unroll
            for (int p = 0; p < 16; p++) {
                uint32_t bd = (uint32_t)((wn + p * 8 + tq) * RSTR + s4 * 32 + tr4);
                uint32_t b0, b1;
                LDS32(b0, aB + bd); LDS32(b1, aB + bd + 16);
                mma16816(c[0][p], a[0], b0, b1);
                mma16816(c[1][p], a[1], b0, b1);
            }
        }
    };

    ldA(sb, 0); ldB(sb + G1_AT, 0); CP_COMMIT();

    const int NIT = Kcat / 64;  // 24 or 48
    for (int it = 0; it < NIT; it++) {
        int s = it & 1;
        uint32_t cur = sb + s * GS_STAGE;
        uint32_t nxt = sb + (1 - s) * GS_STAGE;
        bool more = (it + 1 < NIT);
        if (more) {
            int k0 = (it + 1) * 64;
            ldA(nxt, k0); ldB(nxt + G1_AT, k0); CP_COMMIT();
            CP_WAIT1();
        } else {
            CP_WAIT0();
        }
        __syncthreads();
        compute(cur);
        __syncthreads();
    }

    // epilogue
#pragma unroll
    for (int ms = 0; ms < 2; ms++) {
        int row = m0 + wm + ms * 16 + (lane >> 2);
#pragma unroll
        for (int ns = 0; ns < 16; ns++) {
            int col = n0 + wn + ns * 8 + 2 * (lane & 3);
            float b0 = bias[col], b1 = bias[col + 1];
            if (which == 2) {
                *reinterpret_cast<float2*>(outf + (size_t)row * DOUT + col) =
                    make_float2(fmaxf(c[ms][ns][0] + b0, 0.0f), fmaxf(c[ms][ns][1] + b1, 0.0f));
                *reinterpret_cast<float2*>(outf + (size_t)(row + 8) * DOUT + col) =
                    make_float2(fmaxf(c[ms][ns][2] + b0, 0.0f), fmaxf(c[ms][ns][3] + b1, 0.0f));
            } else {
                int colofs = (which == 1) ? 512 : 0;
#pragma unroll
                for (int half = 0; half < 2; half++) {
                    int rr = row + half * 8;
                    float v0 = c[ms][ns][2 * half] + b0;
                    float v1 = c[ms][ns][2 * half + 1] + b1;
                    __nv_bfloat16 h0, l0, h1, l1;
                    split_hl(v0, h0, l0); split_hl(v1, h1, l1);
                    size_t rb = (size_t)rr * 3072 + colofs + col;
                    *reinterpret_cast<__nv_bfloat162*>(g_A4 + rb)        = __nv_bfloat162(h0, h1);
                    *reinterpret_cast<__nv_bfloat162*>(g_A4 + rb + 1024) = __nv_bfloat162(l0, l1);
                    *reinterpret_cast<__nv_bfloat162*>(g_A4 + rb + 2048) = __nv_bfloat162(h0, h1);
                }
            }
        }
    }
}

// ---------------- launcher (inputs resolved by element count) ----------------
extern "C" void kernel_launch(void* const* d_in, const int* in_sizes, int n_in,
                              void* d_out, int out_size) {
    const float* x = nullptr; const int* adj = nullptr;
    const float *Ws = nullptr, *bs = nullptr, *Wn = nullptr, *bn = nullptr;
    const float *Wc = nullptr, *bc = nullptr;
    for (int i = 0; i < n_in; i++) {
        long long s = in_sizes[i];
        const void* p = d_in[i];
        if (s == (long long)NN * NN)            adj = (const int*)p;
        else if (s == (long long)NN * DIN)      x = (const float*)p;
        else if (s == (long long)2 * DOUT * DOUT) Wc = (const float*)p;
        else if (s == (long long)DIN * DOUT) { if (!Ws) Ws = (const float*)p; else Wn = (const float*)p; }
        else if (s == DOUT) { if (!bs) bs = (const float*)p; else if (!bn) bn = (const float*)p; else bc = (const float*)p; }
    }
    float* out = (float*)d_out;

    cudaFuncSetAttribute(gemm1_kernel, cudaFuncAttributeMaxDynamicSharedMemorySize, G1_SMEM);
    cudaFuncSetAttribute(gemm_small_kernel, cudaFuncAttributeMaxDynamicSharedMemorySize, GS_SMEM);

    prep_x_kernel<<<dim3(16, 256), dim3(32, 8)>>>(x);
    prep_w_kernel<<<2048, 256>>>(Ws, Wn, Wc);
    gemm1_kernel<<<dim3(2, 64), 256, G1_SMEM>>>(adj);
    agg_split_kernel<<<4096, 256>>>();
    gemm_small_kernel<<<dim3(2, 64), 256, GS_SMEM>>>(0, bs, out);
    gemm_small_kernel<<<dim3(2, 64), 256, GS_SMEM>>>(1, bn, out);
    gemm_small_kernel<<<dim3(2, 64), 256, GS_SMEM>>>(2, bc, out);
}

// round 8
// speedup vs baseline: 1.3117x; 1.3117x over previous
#include <cuda_runtime.h>
#include <cuda_fp16.h>
#include <cstdint>

#define NN    8192
#define DIN   512
#define DOUT  512

// ---------------- helpers ----------------
__device__ __forceinline__ uint32_t smem_to_u32(const void* p) {
    uint32_t a;
    asm("{ .reg .u64 t; cvta.to.shared.u64 t, %1; cvt.u32.u64 %0, t; }" : "=r"(a) : "l"(p));
    return a;
}

#define CP_ASYNC16(dst, src) \
    asm volatile("cp.async.cg.shared.global [%0], [%1], 16;" :: "r"(dst), "l"(src) : "memory")
#define CP_COMMIT() asm volatile("cp.async.commit_group;" ::: "memory")
#define CP_WAIT0()  asm volatile("cp.async.wait_group 0;" ::: "memory")
#define CP_WAIT1()  asm volatile("cp.async.wait_group 1;" ::: "memory")

#define LDS32(v, addr) \
    asm volatile("ld.shared.b32 %0, [%1];" : "=r"(v) : "r"(addr))

__device__ __forceinline__ void mma16816(float* c, const uint32_t* a, uint32_t b0, uint32_t b1) {
    asm volatile(
        "mma.sync.aligned.m16n8k16.row.col.f32.f16.f16.f32 "
        "{%0,%1,%2,%3}, {%4,%5,%6,%7}, {%8,%9}, {%0,%1,%2,%3};"
        : "+f"(c[0]), "+f"(c[1]), "+f"(c[2]), "+f"(c[3])
        : "r"(a[0]), "r"(a[1]), "r"(a[2]), "r"(a[3]), "r"(b0), "r"(b1));
}

// ---------------- device-global scratch (all fp16 now) ----------------
__device__ __align__(256) __half g_xT[(size_t)DIN * NN];     // x^T fp16 [512,8192]
__device__ __align__(256) __half g_A2[(size_t)NN * 1536];    // [x_hi | x_lo | x_hi]
__device__ __align__(256) __half g_A3[(size_t)NN * 1536];    // [agg_hi | agg_lo | agg_hi]
__device__ __align__(256) __half g_A4[(size_t)NN * 3072];    // [c_hi | c_lo | c_hi]
__device__ __align__(256) __half g_Bt2[(size_t)DOUT * 1536];
__device__ __align__(256) __half g_Bt3[(size_t)DOUT * 1536];
__device__ __align__(256) __half g_Bt4[(size_t)DOUT * 3072];
__device__ __align__(256) float g_S1[(size_t)NN * DOUT];
__device__ __align__(256) float g_deg[NN];

__device__ __forceinline__ void split_hl(float v, __half& h, __half& l) {
    h = __float2half_rn(v);
    l = __float2half_rn(v - __half2float(h));
}

// ---------------- prep: x -> A2 cat (fp16 hi/lo) + transposed fp16 ----------------
__global__ void prep_x_kernel(const float* __restrict__ x) {
    __shared__ __half sh[32][33];
    int tx = threadIdx.x, ty = threadIdx.y;
    int d0 = blockIdx.x * 32, m0 = blockIdx.y * 32;
#pragma unroll
    for (int r = 0; r < 4; r++) {
        int mm = ty + r * 8, m = m0 + mm;
        float v = x[(size_t)m * DIN + d0 + tx];
        __half h, l; split_hl(v, h, l);
        size_t rb = (size_t)m * 1536 + d0 + tx;
        g_A2[rb] = h; g_A2[rb + 512] = l; g_A2[rb + 1024] = h;
        sh[mm][tx] = h;
    }
    __syncthreads();
#pragma unroll
    for (int r = 0; r < 4; r++) {
        int dd = ty + r * 8, d = d0 + dd, m = m0 + tx;
        g_xT[(size_t)d * NN + m] = sh[tx][dd];
    }
}

// ---------------- prep: weights -> transposed fp16 hi/lo K-concats ----------------
__global__ void prep_w_kernel(const float* __restrict__ Ws, const float* __restrict__ Wn,
                              const float* __restrict__ Wc) {
    int t = blockIdx.x * blockDim.x + threadIdx.x;  // 512*1024 threads
    int n = t & 511, k = t >> 9;
    __half h, l;
    if (k < 512) {
        size_t rb = (size_t)n * 1536 + k;
        split_hl(Ws[(size_t)k * DOUT + n], h, l);
        g_Bt2[rb] = h; g_Bt2[rb + 512] = h; g_Bt2[rb + 1024] = l;
        split_hl(Wn[(size_t)k * DOUT + n], h, l);
        g_Bt3[rb] = h; g_Bt3[rb + 512] = h; g_Bt3[rb + 1024] = l;
    }
    {
        size_t rb = (size_t)n * 3072 + k;
        split_hl(Wc[(size_t)k * DOUT + n], h, l);
        g_Bt4[rb] = h; g_Bt4[rb + 1024] = h; g_Bt4[rb + 2048] = l;
    }
}

// ---------------- agg = S1/max(deg,1) -> A3 cat (fp16 hi/lo) ----------------
__global__ void agg_split_kernel() {
    int t = blockIdx.x * 256 + threadIdx.x;  // NN*128 threads
    int m = t >> 7, d4 = (t & 127) * 4;
    float inv = 1.0f / fmaxf(g_deg[m], 1.0f);
    float4 s = *reinterpret_cast<const float4*>(g_S1 + (size_t)m * DOUT + d4);
    __half h0, l0, h1, l1, h2, l2, h3, l3;
    split_hl(s.x * inv, h0, l0); split_hl(s.y * inv, h1, l1);
    split_hl(s.z * inv, h2, l2); split_hl(s.w * inv, h3, l3);
    size_t rb = (size_t)m * 1536 + d4;
    __half2* p;
    p = reinterpret_cast<__half2*>(g_A3 + rb);
    p[0] = __halves2half2(h0, h1); p[1] = __halves2half2(h2, h3);
    p = reinterpret_cast<__half2*>(g_A3 + rb + 512);
    p[0] = __halves2half2(l0, l1); p[1] = __halves2half2(l2, l3);
    p = reinterpret_cast<__half2*>(g_A3 + rb + 1024);
    p[0] = __halves2half2(h0, h1); p[1] = __halves2half2(h2, h3);
}

// ============================================================================
// Padded-linear smem layout: row stride 144 B (64 fp16 data + 16 B pad).
// Fragment regs via LDS32 per PTX m16n8k16 layouts (verified working in R7):
//   a0=(m,k2) a1=(m+8,k2) a2=(m,k2+8) a3=(m+8,k2+8); b0=(k2,n) b1=(k2+8,n)
// ============================================================================
static constexpr int RSTR = 144;
static constexpr int AT_SZ = 128 * RSTR;            // 18432
static constexpr int BT_SZ = 256 * RSTR;            // 36864
static constexpr int G1_STAGE = AT_SZ + BT_SZ;      // 55296 (single-pass fp16: no Bl)
static constexpr int G1_SMEM  = 1024 + 2 * G1_STAGE;  // 111616

__global__ void __launch_bounds__(256, 1)
gemm1_kernel(const int* __restrict__ adj) {
    extern __shared__ char smem[];
    uint32_t sb = smem_to_u32(smem);
    int tid = threadIdx.x, wid = tid >> 5, lane = tid & 31;
    int m0 = blockIdx.y * 128, n0 = blockIdx.x * 256;
    bool dodeg = (blockIdx.x == 0);
    int* degsm = reinterpret_cast<int*>(smem);
    if (tid < 128) degsm[tid] = 0;

    const int wm = (wid & 3) * 32;     // warp m-offset
    const int wn = (wid >> 2) * 128;   // warp n-offset

    float c[2][16][4];
#pragma unroll
    for (int i = 0; i < 2; i++)
#pragma unroll
        for (int j = 0; j < 16; j++)
#pragma unroll
            for (int q = 0; q < 4; q++) c[i][j][q] = 0.0f;

    int4 av[4][2];
    int dacc[4] = {0, 0, 0, 0};

    auto ldA = [&](int k0) {
#pragma unroll
        for (int i = 0; i < 4; i++) {
            int idx = i * 256 + tid;
            int r = idx >> 3, cc = idx & 7;
            const int4* p = reinterpret_cast<const int4*>(
                adj + (size_t)(m0 + r) * NN + k0 + cc * 8);
            av[i][0] = p[0]; av[i][1] = p[1];
        }
    };
    auto stA = [&](uint32_t abase) {
#pragma unroll
        for (int i = 0; i < 4; i++) {
            int idx = i * 256 + tid;
            int r = idx >> 3, cc = idx & 7;
            // fp16 1.0 = 0x3C00
            uint32_t p0 = ((av[i][0].x > 0) ? 0x3C00u : 0u) | ((av[i][0].y > 0) ? 0x3C000000u : 0u);
            uint32_t p1 = ((av[i][0].z > 0) ? 0x3C00u : 0u) | ((av[i][0].w > 0) ? 0x3C000000u : 0u);
            uint32_t p2 = ((av[i][1].x > 0) ? 0x3C00u : 0u) | ((av[i][1].y > 0) ? 0x3C000000u : 0u);
            uint32_t p3 = ((av[i][1].z > 0) ? 0x3C00u : 0u) | ((av[i][1].w > 0) ? 0x3C000000u : 0u);
            if (dodeg)
                dacc[i] += (av[i][0].x > 0) + (av[i][0].y > 0) + (av[i][0].z > 0) + (av[i][0].w > 0)
                         + (av[i][1].x > 0) + (av[i][1].y > 0) + (av[i][1].z > 0) + (av[i][1].w > 0);
            asm volatile("st.shared.v4.b32 [%0], {%1,%2,%3,%4};"
                         :: "r"(abase + (uint32_t)(r * RSTR + cc * 16)),
                            "r"(p0), "r"(p1), "r"(p2), "r"(p3) : "memory");
        }
    };
    auto ldB = [&](uint32_t bbase, int k0) {
#pragma unroll
        for (int i = 0; i < 8; i++) {
            int idx = i * 256 + tid;
            int r = idx >> 3, cc = idx & 7;
            CP_ASYNC16(bbase + (uint32_t)(r * RSTR + cc * 16),
                       reinterpret_cast<const char*>(g_xT) + ((size_t)(n0 + r) * NN + k0 + cc * 8) * 2);
        }
    };
    auto compute = [&](uint32_t base) {
        uint32_t aB = base + AT_SZ;
        int tq = lane >> 2;          // 0..7
        int tr4 = (lane & 3) * 4;    // k-pair byte offset
#pragma unroll
        for (int s4 = 0; s4 < 4; s4++) {
            uint32_t a[2][4];
#pragma unroll
            for (int ms = 0; ms < 2; ms++) {
                uint32_t ad = base + (uint32_t)((wm + ms * 16 + tq) * RSTR + s4 * 32 + tr4);
                LDS32(a[ms][0], ad);
                LDS32(a[ms][1], ad + 8 * RSTR);
                LDS32(a[ms][2], ad + 16);
                LDS32(a[ms][3], ad + 8 * RSTR + 16);
            }
#pragma unroll
            for (int p = 0; p < 16; p++) {
                uint32_t bd = (uint32_t)((wn + p * 8 + tq) * RSTR + s4 * 32 + tr4);
                uint32_t b0, b1;
                LDS32(b0, aB + bd); LDS32(b1, aB + bd + 16);
                mma16816(c[0][p], a[0], b0, b1);
                mma16816(c[1][p], a[1], b0, b1);
            }
        }
    };

    // prologue
    uint32_t st0 = sb + 1024;
    ldA(0);
    ldB(st0 + AT_SZ, 0);
    CP_COMMIT();
    stA(st0);

    const int NIT = NN / 64;  // 128
    for (int it = 0; it < NIT; it++) {
        int s = it & 1;
        uint32_t cur = sb + 1024 + s * G1_STAGE;
        uint32_t nxt = sb + 1024 + (1 - s) * G1_STAGE;
        bool more = (it + 1 < NIT);
        if (more) {
            int k0 = (it + 1) * 64;
            ldA(k0);
            ldB(nxt + AT_SZ, k0);
            CP_COMMIT();
            CP_WAIT1();
        } else {
            CP_WAIT0();
        }
        __syncthreads();
        compute(cur);
        if (more) stA(nxt);
        __syncthreads();
    }

    // epilogue: raw sums to g_S1
#pragma unroll
    for (int ms = 0; ms < 2; ms++) {
        int row = m0 + wm + ms * 16 + (lane >> 2);
#pragma unroll
        for (int ns = 0; ns < 16; ns++) {
            int col = n0 + wn + ns * 8 + 2 * (lane & 3);
            *reinterpret_cast<float2*>(g_S1 + (size_t)row * DOUT + col) =
                make_float2(c[ms][ns][0], c[ms][ns][1]);
            *reinterpret_cast<float2*>(g_S1 + (size_t)(row + 8) * DOUT + col) =
                make_float2(c[ms][ns][2], c[ms][ns][3]);
        }
    }
    if (dodeg) {
#pragma unroll
        for (int i = 0; i < 4; i++) atomicAdd(&degsm[(i * 256 + tid) >> 3], dacc[i]);
        __syncthreads();
        if (tid < 128) g_deg[m0 + tid] = (float)degsm[tid];
    }
}

// ============================================================================
// Small GEMMs: C[8192,512] = A[8192,Kcat] @ Bt[512,Kcat]^T + epilogue
// which: 0 self_f -> g_A4 cols [0,512); 1 nb_f -> g_A4 cols [512,1024);
//        2 final  -> bias+relu -> out
// ============================================================================
static constexpr int GS_STAGE = AT_SZ + BT_SZ;      // 55296
static constexpr int GS_SMEM  = 2 * GS_STAGE;       // 110592

__global__ void __launch_bounds__(256, 1)
gemm_small_kernel(int which, const float* __restrict__ bias, float* __restrict__ outf) {
    extern __shared__ char smem[];
    uint32_t sb = smem_to_u32(smem);
    int tid = threadIdx.x, wid = tid >> 5, lane = tid & 31;
    int m0 = blockIdx.y * 128, n0 = blockIdx.x * 256;

    const __half *A, *B;
    int Kcat;
    if (which == 0)      { A = g_A2; B = g_Bt2; Kcat = 1536; }
    else if (which == 1) { A = g_A3; B = g_Bt3; Kcat = 1536; }
    else                 { A = g_A4; B = g_Bt4; Kcat = 3072; }

    const int wm = (wid & 3) * 32, wn = (wid >> 2) * 128;

    float c[2][16][4];
#pragma unroll
    for (int i = 0; i < 2; i++)
#pragma unroll
        for (int j = 0; j < 16; j++)
#pragma unroll
            for (int q = 0; q < 4; q++) c[i][j][q] = 0.0f;

    auto ldA = [&](uint32_t abase, int k0) {
#pragma unroll
        for (int i = 0; i < 4; i++) {
            int idx = i * 256 + tid;
            int r = idx >> 3, cc = idx & 7;
            CP_ASYNC16(abase + (uint32_t)(r * RSTR + cc * 16),
                       reinterpret_cast<const char*>(A) + ((size_t)(m0 + r) * Kcat + k0 + cc * 8) * 2);
        }
    };
    auto ldB = [&](uint32_t bbase, int k0) {
#pragma unroll
        for (int i = 0; i < 8; i++) {
            int idx = i * 256 + tid;
            int r = idx >> 3, cc = idx & 7;
            CP_ASYNC16(bbase + (uint32_t)(r * RSTR + cc * 16),
                       reinterpret_cast<const char*>(B) + ((size_t)(n0 + r) * Kcat + k0 + cc * 8) * 2);
        }
    };
    auto compute = [&](uint32_t base) {
        uint32_t aB = base + AT_SZ;
        int tq = lane >> 2;
        int tr4 = (lane & 3) * 4;
#pragma unroll
        for (int s4 = 0; s4 < 4; s4++) {
            uint32_t a[2][4];
#pragma unroll
            for (int ms = 0; ms < 2; ms++) {
                uint32_t ad = base + (uint32_t)((wm + ms * 16 + tq) * RSTR + s4 * 32 + tr4);
                LDS32(a[ms][0], ad);
                LDS32(a[ms][1], ad + 8 * RSTR);
                LDS32(a[ms][2], ad + 16);
                LDS32(a[ms][3], ad + 8 * RSTR + 16);
            }
#pragma unroll
            for (int p = 0; p < 16; p++) {
                uint32_t bd = (uint32_t)((wn + p * 8 + tq) * RSTR + s4 * 32 + tr4);
                uint32_t b0, b1;
                LDS32(b0, aB + bd); LDS32(b1, aB + bd + 16);
                mma16816(c[0][p], a[0], b0, b1);
                mma16816(c[1][p], a[1], b0, b1);
            }
        }
    };

    ldA(sb, 0); ldB(sb + AT_SZ, 0); CP_COMMIT();

    const int NIT = Kcat / 64;  // 24 or 48
    for (int it = 0; it < NIT; it++) {
        int s = it & 1;
        uint32_t cur = sb + s * GS_STAGE;
        uint32_t nxt = sb + (1 - s) * GS_STAGE;
        bool more = (it + 1 < NIT);
        if (more) {
            int k0 = (it + 1) * 64;
            ldA(nxt, k0); ldB(nxt + AT_SZ, k0); CP_COMMIT();
            CP_WAIT1();
        } else {
            CP_WAIT0();
        }
        __syncthreads();
        compute(cur);
        __syncthreads();
    }

    // epilogue
#pragma unroll
    for (int ms = 0; ms < 2; ms++) {
        int row = m0 + wm + ms * 16 + (lane >> 2);
#pragma unroll
        for (int ns = 0; ns < 16; ns++) {
            int col = n0 + wn + ns * 8 + 2 * (lane & 3);
            float b0 = bias[col], b1 = bias[col + 1];
            if (which == 2) {
                *reinterpret_cast<float2*>(outf + (size_t)row * DOUT + col) =
                    make_float2(fmaxf(c[ms][ns][0] + b0, 0.0f), fmaxf(c[ms][ns][1] + b1, 0.0f));
                *reinterpret_cast<float2*>(outf + (size_t)(row + 8) * DOUT + col) =
                    make_float2(fmaxf(c[ms][ns][2] + b0, 0.0f), fmaxf(c[ms][ns][3] + b1, 0.0f));
            } else {
                int colofs = (which == 1) ? 512 : 0;
#pragma unroll
                for (int half = 0; half < 2; half++) {
                    int rr = row + half * 8;
                    float v0 = c[ms][ns][2 * half] + b0;
                    float v1 = c[ms][ns][2 * half + 1] + b1;
                    __half h0, l0, h1, l1;
                    split_hl(v0, h0, l0); split_hl(v1, h1, l1);
                    size_t rb = (size_t)rr * 3072 + colofs + col;
                    *reinterpret_cast<__half2*>(g_A4 + rb)        = __halves2half2(h0, h1);
                    *reinterpret_cast<__half2*>(g_A4 + rb + 1024) = __halves2half2(l0, l1);
                    *reinterpret_cast<__half2*>(g_A4 + rb + 2048) = __halves2half2(h0, h1);
                }
            }
        }
    }
}

// ---------------- launcher (inputs resolved by element count) ----------------
extern "C" void kernel_launch(void* const* d_in, const int* in_sizes, int n_in,
                              void* d_out, int out_size) {
    const float* x = nullptr; const int* adj = nullptr;
    const float *Ws = nullptr, *bs = nullptr, *Wn = nullptr, *bn = nullptr;
    const float *Wc = nullptr, *bc = nullptr;
    for (int i = 0; i < n_in; i++) {
        long long s = in_sizes[i];
        const void* p = d_in[i];
        if (s == (long long)NN * NN)            adj = (const int*)p;
        else if (s == (long long)NN * DIN)      x = (const float*)p;
        else if (s == (long long)2 * DOUT * DOUT) Wc = (const float*)p;
        else if (s == (long long)DIN * DOUT) { if (!Ws) Ws = (const float*)p; else Wn = (const float*)p; }
        else if (s == DOUT) { if (!bs) bs = (const float*)p; else if (!bn) bn = (const float*)p; else bc = (const float*)p; }
    }
    float* out = (float*)d_out;

    cudaFuncSetAttribute(gemm1_kernel, cudaFuncAttributeMaxDynamicSharedMemorySize, G1_SMEM);
    cudaFuncSetAttribute(gemm_small_kernel, cudaFuncAttributeMaxDynamicSharedMemorySize, GS_SMEM);

    prep_x_kernel<<<dim3(16, 256), dim3(32, 8)>>>(x);
    prep_w_kernel<<<2048, 256>>>(Ws, Wn, Wc);
    gemm1_kernel<<<dim3(2, 64), 256, G1_SMEM>>>(adj);
    agg_split_kernel<<<4096, 256>>>();
    gemm_small_kernel<<<dim3(2, 64), 256, GS_SMEM>>>(0, bs, out);
    gemm_small_kernel<<<dim3(2, 64), 256, GS_SMEM>>>(1, bn, out);
    gemm_small_kernel<<<dim3(2, 64), 256, GS_SMEM>>>(2, bc, out);
}

// round 9
// speedup vs baseline: 1.8334x; 1.3977x over previous
#include <cuda_runtime.h>
#include <cuda_fp16.h>
#include <cstdint>

#define NN    8192
#define DIN   512
#define DOUT  512

// ---------------- helpers ----------------
__device__ __forceinline__ uint32_t smem_to_u32(const void* p) {
    uint32_t a;
    asm("{ .reg .u64 t; cvta.to.shared.u64 t, %1; cvt.u32.u64 %0, t; }" : "=r"(a) : "l"(p));
    return a;
}

#define CP_ASYNC16(dst, src) \
    asm volatile("cp.async.cg.shared.global [%0], [%1], 16;" :: "r"(dst), "l"(src) : "memory")
#define CP_COMMIT() asm volatile("cp.async.commit_group;" ::: "memory")
#define CP_WAIT0()  asm volatile("cp.async.wait_group 0;" ::: "memory")
#define CP_WAIT1()  asm volatile("cp.async.wait_group 1;" ::: "memory")

#define LDS32(v, addr) \
    asm volatile("ld.shared.b32 %0, [%1];" : "=r"(v) : "r"(addr))

__device__ __forceinline__ void mma16816(float* c, const uint32_t* a, uint32_t b0, uint32_t b1) {
    asm volatile(
        "mma.sync.aligned.m16n8k16.row.col.f32.f16.f16.f32 "
        "{%0,%1,%2,%3}, {%4,%5,%6,%7}, {%8,%9}, {%0,%1,%2,%3};"
        : "+f"(c[0]), "+f"(c[1]), "+f"(c[2]), "+f"(c[3])
        : "r"(a[0]), "r"(a[1]), "r"(a[2]), "r"(a[3]), "r"(b0), "r"(b1));
}

// ---------------- device-global scratch (single-precision-path fp16) ----------------
__device__ __align__(256) __half g_xT[(size_t)DIN * NN];      // x^T [512,8192]
__device__ __align__(256) __half g_A2[(size_t)NN * DIN];      // x fp16 [8192,512]
__device__ __align__(256) __half g_A3[(size_t)NN * DIN];      // agg fp16 [8192,512]
__device__ __align__(256) __half g_A4[(size_t)NN * 1024];     // [self_f | nb_f] fp16
__device__ __align__(256) __half g_Bt2[(size_t)DOUT * DIN];   // W_self^T [n][k]
__device__ __align__(256) __half g_Bt3[(size_t)DOUT * DIN];   // W_nb^T
__device__ __align__(256) __half g_Bt4[(size_t)DOUT * 1024];  // W_comb^T
__device__ __align__(256) float g_S1[(size_t)NN * DOUT];
__device__ __align__(256) float g_deg[NN];

// ---------------- prep: x -> A2 fp16 + transposed fp16 ----------------
__global__ void prep_x_kernel(const float* __restrict__ x) {
    __shared__ __half sh[32][33];
    int tx = threadIdx.x, ty = threadIdx.y;
    int d0 = blockIdx.x * 32, m0 = blockIdx.y * 32;
#pragma unroll
    for (int r = 0; r < 4; r++) {
        int mm = ty + r * 8, m = m0 + mm;
        __half h = __float2half_rn(x[(size_t)m * DIN + d0 + tx]);
        g_A2[(size_t)m * DIN + d0 + tx] = h;
        sh[mm][tx] = h;
    }
    __syncthreads();
#pragma unroll
    for (int r = 0; r < 4; r++) {
        int dd = ty + r * 8, d = d0 + dd, m = m0 + tx;
        g_xT[(size_t)d * NN + m] = sh[tx][dd];
    }
}

// ---------------- prep: weights -> transposed fp16 ----------------
__global__ void prep_w_kernel(const float* __restrict__ Ws, const float* __restrict__ Wn,
                              const float* __restrict__ Wc) {
    int t = blockIdx.x * blockDim.x + threadIdx.x;  // 512*1024 threads
    int n = t & 511, k = t >> 9;                    // k in [0,1024)
    if (k < 512) {
        g_Bt2[(size_t)n * DIN + k] = __float2half_rn(Ws[(size_t)k * DOUT + n]);
        g_Bt3[(size_t)n * DIN + k] = __float2half_rn(Wn[(size_t)k * DOUT + n]);
    }
    g_Bt4[(size_t)n * 1024 + k] = __float2half_rn(Wc[(size_t)k * DOUT + n]);
}

// ---------------- agg = S1/max(deg,1) -> A3 fp16 ----------------
__global__ void agg_split_kernel() {
    int t = blockIdx.x * 256 + threadIdx.x;  // NN*128 threads
    int m = t >> 7, d4 = (t & 127) * 4;
    float inv = 1.0f / fmaxf(g_deg[m], 1.0f);
    float4 s = *reinterpret_cast<const float4*>(g_S1 + (size_t)m * DOUT + d4);
    __half2* p = reinterpret_cast<__half2*>(g_A3 + (size_t)m * DIN + d4);
    p[0] = __halves2half2(__float2half_rn(s.x * inv), __float2half_rn(s.y * inv));
    p[1] = __halves2half2(__float2half_rn(s.z * inv), __float2half_rn(s.w * inv));
}

// ============================================================================
// Padded-linear smem layout: row stride 144 B (64 fp16 data + 16 B pad).
// Fragment regs via LDS32 per PTX m16n8k16 layouts (verified R7/R8):
//   a0=(m,k2) a1=(m+8,k2) a2=(m,k2+8) a3=(m+8,k2+8); b0=(k2,n) b1=(k2+8,n)
// ============================================================================
static constexpr int RSTR = 144;
static constexpr int AT_SZ = 128 * RSTR;            // 18432
static constexpr int BT_SZ = 256 * RSTR;            // 36864
static constexpr int G1_STAGE = AT_SZ + BT_SZ;      // 55296
static constexpr int G1_SMEM  = 1024 + 2 * G1_STAGE;  // 111616

__global__ void __launch_bounds__(256, 1)
gemm1_kernel(const int* __restrict__ adj) {
    extern __shared__ char smem[];
    uint32_t sb = smem_to_u32(smem);
    int tid = threadIdx.x, wid = tid >> 5, lane = tid & 31;
    int m0 = blockIdx.y * 128, n0 = blockIdx.x * 256;
    bool dodeg = (blockIdx.x == 0);
    int* degsm = reinterpret_cast<int*>(smem);
    if (tid < 128) degsm[tid] = 0;

    const int wm = (wid & 3) * 32;     // warp m-offset
    const int wn = (wid >> 2) * 128;   // warp n-offset

    float c[2][16][4];
#pragma unroll
    for (int i = 0; i < 2; i++)
#pragma unroll
        for (int j = 0; j < 16; j++)
#pragma unroll
            for (int q = 0; q < 4; q++) c[i][j][q] = 0.0f;

    int4 av[4][2];
    int dacc[4] = {0, 0, 0, 0};

    auto ldA = [&](int k0) {
#pragma unroll
        for (int i = 0; i < 4; i++) {
            int idx = i * 256 + tid;
            int r = idx >> 3, cc = idx & 7;
            const int4* p = reinterpret_cast<const int4*>(
                adj + (size_t)(m0 + r) * NN + k0 + cc * 8);
            av[i][0] = p[0]; av[i][1] = p[1];
        }
    };
    auto stA = [&](uint32_t abase) {
#pragma unroll
        for (int i = 0; i < 4; i++) {
            int idx = i * 256 + tid;
            int r = idx >> 3, cc = idx & 7;
            // fp16 1.0 = 0x3C00
            uint32_t p0 = ((av[i][0].x > 0) ? 0x3C00u : 0u) | ((av[i][0].y > 0) ? 0x3C000000u : 0u);
            uint32_t p1 = ((av[i][0].z > 0) ? 0x3C00u : 0u) | ((av[i][0].w > 0) ? 0x3C000000u : 0u);
            uint32_t p2 = ((av[i][1].x > 0) ? 0x3C00u : 0u) | ((av[i][1].y > 0) ? 0x3C000000u : 0u);
            uint32_t p3 = ((av[i][1].z > 0) ? 0x3C00u : 0u) | ((av[i][1].w > 0) ? 0x3C000000u : 0u);
            if (dodeg)
                dacc[i] += (av[i][0].x > 0) + (av[i][0].y > 0) + (av[i][0].z > 0) + (av[i][0].w > 0)
                         + (av[i][1].x > 0) + (av[i][1].y > 0) + (av[i][1].z > 0) + (av[i][1].w > 0);
            asm volatile("st.shared.v4.b32 [%0], {%1,%2,%3,%4};"
                         :: "r"(abase + (uint32_t)(r * RSTR + cc * 16)),
                            "r"(p0), "r"(p1), "r"(p2), "r"(p3) : "memory");
        }
    };
    auto ldB = [&](uint32_t bbase, int k0) {
#pragma unroll
        for (int i = 0; i < 8; i++) {
            int idx = i * 256 + tid;
            int r = idx >> 3, cc = idx & 7;
            CP_ASYNC16(bbase + (uint32_t)(r * RSTR + cc * 16),
                       reinterpret_cast<const char*>(g_xT) + ((size_t)(n0 + r) * NN + k0 + cc * 8) * 2);
        }
    };
    auto compute = [&](uint32_t base) {
        uint32_t aB = base + AT_SZ;
        int tq = lane >> 2;          // 0..7
        int tr4 = (lane & 3) * 4;    // k-pair byte offset
#pragma unroll
        for (int s4 = 0; s4 < 4; s4++) {
            uint32_t a[2][4];
#pragma unroll
            for (int ms = 0; ms < 2; ms++) {
                uint32_t ad = base + (uint32_t)((wm + ms * 16 + tq) * RSTR + s4 * 32 + tr4);
                LDS32(a[ms][0], ad);
                LDS32(a[ms][1], ad + 8 * RSTR);
                LDS32(a[ms][2], ad + 16);
                LDS32(a[ms][3], ad + 8 * RSTR + 16);
            }
#pragma unroll
            for (int p = 0; p < 16; p++) {
                uint32_t bd = (uint32_t)((wn + p * 8 + tq) * RSTR + s4 * 32 + tr4);
                uint32_t b0, b1;
                LDS32(b0, aB + bd); LDS32(b1, aB + bd + 16);
                mma16816(c[0][p], a[0], b0, b1);
                mma16816(c[1][p], a[1], b0, b1);
            }
        }
    };

    // prologue
    uint32_t st0 = sb + 1024;
    ldA(0);
    ldB(st0 + AT_SZ, 0);
    CP_COMMIT();
    stA(st0);

    const int NIT = NN / 64;  // 128
    for (int it = 0; it < NIT; it++) {
        int s = it & 1;
        uint32_t cur = sb + 1024 + s * G1_STAGE;
        uint32_t nxt = sb + 1024 + (1 - s) * G1_STAGE;
        bool more = (it + 1 < NIT);
        if (more) {
            int k0 = (it + 1) * 64;
            ldA(k0);
            ldB(nxt + AT_SZ, k0);
            CP_COMMIT();
            CP_WAIT1();
        } else {
            CP_WAIT0();
        }
        __syncthreads();
        compute(cur);
        if (more) stA(nxt);
        __syncthreads();
    }

    // epilogue: raw sums to g_S1
#pragma unroll
    for (int ms = 0; ms < 2; ms++) {
        int row = m0 + wm + ms * 16 + (lane >> 2);
#pragma unroll
        for (int ns = 0; ns < 16; ns++) {
            int col = n0 + wn + ns * 8 + 2 * (lane & 3);
            *reinterpret_cast<float2*>(g_S1 + (size_t)row * DOUT + col) =
                make_float2(c[ms][ns][0], c[ms][ns][1]);
            *reinterpret_cast<float2*>(g_S1 + (size_t)(row + 8) * DOUT + col) =
                make_float2(c[ms][ns][2], c[ms][ns][3]);
        }
    }
    if (dodeg) {
#pragma unroll
        for (int i = 0; i < 4; i++) atomicAdd(&degsm[(i * 256 + tid) >> 3], dacc[i]);
        __syncthreads();
        if (tid < 128) g_deg[m0 + tid] = (float)degsm[tid];
    }
}

// ============================================================================
// Small GEMMs (single-pass fp16): C[8192,512] = A[8192,K] @ Bt[512,K]^T
// which: 0 self_f (K=512) -> g_A4 cols [0,512)
//        1 nb_f   (K=512) -> g_A4 cols [512,1024)
//        2 final  (K=1024) -> bias+relu -> out
// ============================================================================
static constexpr int GS_STAGE = AT_SZ + BT_SZ;      // 55296
static constexpr int GS_SMEM  = 2 * GS_STAGE;       // 110592

__global__ void __launch_bounds__(256, 1)
gemm_small_kernel(int which, const float* __restrict__ bias, float* __restrict__ outf) {
    extern __shared__ char smem[];
    uint32_t sb = smem_to_u32(smem);
    int tid = threadIdx.x, wid = tid >> 5, lane = tid & 31;
    int m0 = blockIdx.y * 128, n0 = blockIdx.x * 256;

    const __half *A, *B;
    int Kcat;
    if (which == 0)      { A = g_A2; B = g_Bt2; Kcat = 512; }
    else if (which == 1) { A = g_A3; B = g_Bt3; Kcat = 512; }
    else                 { A = g_A4; B = g_Bt4; Kcat = 1024; }

    const int wm = (wid & 3) * 32, wn = (wid >> 2) * 128;

    float c[2][16][4];
#pragma unroll
    for (int i = 0; i < 2; i++)
#pragma unroll
        for (int j = 0; j < 16; j++)
#pragma unroll
            for (int q = 0; q < 4; q++) c[i][j][q] = 0.0f;

    auto ldA = [&](uint32_t abase, int k0) {
#pragma unroll
        for (int i = 0; i < 4; i++) {
            int idx = i * 256 + tid;
            int r = idx >> 3, cc = idx & 7;
            CP_ASYNC16(abase + (uint32_t)(r * RSTR + cc * 16),
                       reinterpret_cast<const char*>(A) + ((size_t)(m0 + r) * Kcat + k0 + cc * 8) * 2);
        }
    };
    auto ldB = [&](uint32_t bbase, int k0) {
#pragma unroll
        for (int i = 0; i < 8; i++) {
            int idx = i * 256 + tid;
            int r = idx >> 3, cc = idx & 7;
            CP_ASYNC16(bbase + (uint32_t)(r * RSTR + cc * 16),
                       reinterpret_cast<const char*>(B) + ((size_t)(n0 + r) * Kcat + k0 + cc * 8) * 2);
        }
    };
    auto compute = [&](uint32_t base) {
        uint32_t aB = base + AT_SZ;
        int tq = lane >> 2;
        int tr4 = (lane & 3) * 4;
#pragma unroll
        for (int s4 = 0; s4 < 4; s4++) {
            uint32_t a[2][4];
#pragma unroll
            for (int ms = 0; ms < 2; ms++) {
                uint32_t ad = base + (uint32_t)((wm + ms * 16 + tq) * RSTR + s4 * 32 + tr4);
                LDS32(a[ms][0], ad);
                LDS32(a[ms][1], ad + 8 * RSTR);
                LDS32(a[ms][2], ad + 16);
                LDS32(a[ms][3], ad + 8 * RSTR + 16);
            }
#pragma unroll
            for (int p = 0; p < 16; p++) {
                uint32_t bd = (uint32_t)((wn + p * 8 + tq) * RSTR + s4 * 32 + tr4);
                uint32_t b0, b1;
                LDS32(b0, aB + bd); LDS32(b1, aB + bd + 16);
                mma16816(c[0][p], a[0], b0, b1);
                mma16816(c[1][p], a[1], b0, b1);
            }
        }
    };

    ldA(sb, 0); ldB(sb + AT_SZ, 0); CP_COMMIT();

    const int NIT = Kcat / 64;  // 8 or 16
    for (int it = 0; it < NIT; it++) {
        int s = it & 1;
        uint32_t cur = sb + s * GS_STAGE;
        uint32_t nxt = sb + (1 - s) * GS_STAGE;
        bool more = (it + 1 < NIT);
        if (more) {
            int k0 = (it + 1) * 64;
            ldA(nxt, k0); ldB(nxt + AT_SZ, k0); CP_COMMIT();
            CP_WAIT1();
        } else {
            CP_WAIT0();
        }
        __syncthreads();
        compute(cur);
        __syncthreads();
    }

    // epilogue
#pragma unroll
    for (int ms = 0; ms < 2; ms++) {
        int row = m0 + wm + ms * 16 + (lane >> 2);
#pragma unroll
        for (int ns = 0; ns < 16; ns++) {
            int col = n0 + wn + ns * 8 + 2 * (lane & 3);
            float b0 = bias[col], b1 = bias[col + 1];
            if (which == 2) {
                *reinterpret_cast<float2*>(outf + (size_t)row * DOUT + col) =
                    make_float2(fmaxf(c[ms][ns][0] + b0, 0.0f), fmaxf(c[ms][ns][1] + b1, 0.0f));
                *reinterpret_cast<float2*>(outf + (size_t)(row + 8) * DOUT + col) =
                    make_float2(fmaxf(c[ms][ns][2] + b0, 0.0f), fmaxf(c[ms][ns][3] + b1, 0.0f));
            } else {
                int colofs = (which == 1) ? 512 : 0;
#pragma unroll
                for (int half = 0; half < 2; half++) {
                    int rr = row + half * 8;
                    __half h0 = __float2half_rn(c[ms][ns][2 * half] + b0);
                    __half h1 = __float2half_rn(c[ms][ns][2 * half + 1] + b1);
                    *reinterpret_cast<__half2*>(g_A4 + (size_t)rr * 1024 + colofs + col) =
                        __halves2half2(h0, h1);
                }
            }
        }
    }
}

// ---------------- launcher (inputs resolved by element count) ----------------
extern "C" void kernel_launch(void* const* d_in, const int* in_sizes, int n_in,
                              void* d_out, int out_size) {
    const float* x = nullptr; const int* adj = nullptr;
    const float *Ws = nullptr, *bs = nullptr, *Wn = nullptr, *bn = nullptr;
    const float *Wc = nullptr, *bc = nullptr;
    for (int i = 0; i < n_in; i++) {
        long long s = in_sizes[i];
        const void* p = d_in[i];
        if (s == (long long)NN * NN)            adj = (const int*)p;
        else if (s == (long long)NN * DIN)      x = (const float*)p;
        else if (s == (long long)2 * DOUT * DOUT) Wc = (const float*)p;
        else if (s == (long long)DIN * DOUT) { if (!Ws) Ws = (const float*)p; else Wn = (const float*)p; }
        else if (s == DOUT) { if (!bs) bs = (const float*)p; else if (!bn) bn = (const float*)p; else bc = (const float*)p; }
    }
    float* out = (float*)d_out;

    cudaFuncSetAttribute(gemm1_kernel, cudaFuncAttributeMaxDynamicSharedMemorySize, G1_SMEM);
    cudaFuncSetAttribute(gemm_small_kernel, cudaFuncAttributeMaxDynamicSharedMemorySize, GS_SMEM);

    prep_x_kernel<<<dim3(16, 256), dim3(32, 8)>>>(x);
    prep_w_kernel<<<2048, 256>>>(Ws, Wn, Wc);
    gemm1_kernel<<<dim3(2, 64), 256, G1_SMEM>>>(adj);
    agg_split_kernel<<<4096, 256>>>();
    gemm_small_kernel<<<dim3(2, 64), 256, GS_SMEM>>>(0, bs, out);
    gemm_small_kernel<<<dim3(2, 64), 256, GS_SMEM>>>(1, bn, out);
    gemm_small_kernel<<<dim3(2, 64), 256, GS_SMEM>>>(2, bc, out);
}